// round 1
// baseline (speedup 1.0000x reference)
#include <cuda_runtime.h>
#include <math.h>

#define Bz 4
#define Sz 2048
#define Ez 1024
#define Hz 4
#define Dz 256
#define BHz (Bz*Hz)
#define MASKVAL (-3.4028234663852886e38f)

#define OUT0  (Bz*Sz*Ez)          // 8388608
#define MEMSZ (Bz*Hz*Dz*Dz)       // 1048576
#define ZSZ   (Bz*Hz*Dz)          // 4096

// ---- scratch (static device allocs; no cudaMalloc allowed) ----
__device__ float g_q [Bz*Hz*Sz*Dz];
__device__ float g_k [Bz*Hz*Sz*Dz];
__device__ float g_v [Bz*Hz*Sz*Dz];
__device__ float g_sq[Bz*Hz*Sz*Dz];
__device__ float g_sk[Bz*Hz*Sz*Dz];
__device__ float g_u [Bz*Hz*Sz*Dz];
__device__ float g_attnmix[Bz*Sz*Ez];
__device__ float g_scores[(size_t)BHz*Sz*Sz];  // 268 MB
__device__ float g_qden[BHz*Sz];
__device__ float g_kden[BHz*Sz];

// =====================================================================
// 128x128x8 fp32 tile GEMM core pieces (256 threads, 8x8 microtile)
// =====================================================================

#define GEMM_PROLOGUE()                                   \
    __shared__ float As[8][128];                          \
    __shared__ float Bs[8][128];                          \
    int tid = threadIdx.x;                                \
    int ty = tid >> 4, tx = tid & 15;                     \
    float acc[8][8];                                      \
    _Pragma("unroll")                                     \
    for (int i = 0; i < 8; i++)                           \
        _Pragma("unroll")                                 \
        for (int j = 0; j < 8; j++) acc[i][j] = 0.f;

#define GEMM_COMPUTE()                                                    \
    __syncthreads();                                                      \
    _Pragma("unroll")                                                     \
    for (int kk = 0; kk < 8; kk++) {                                      \
        float4 a0 = *(float4*)(&As[kk][ty*8]);                            \
        float4 a1 = *(float4*)(&As[kk][ty*8+4]);                          \
        float4 b0 = *(float4*)(&Bs[kk][tx*8]);                            \
        float4 b1 = *(float4*)(&Bs[kk][tx*8+4]);                          \
        float ar[8] = {a0.x,a0.y,a0.z,a0.w,a1.x,a1.y,a1.z,a1.w};          \
        float br[8] = {b0.x,b0.y,b0.z,b0.w,b1.x,b1.y,b1.z,b1.w};          \
        _Pragma("unroll")                                                 \
        for (int i = 0; i < 8; i++)                                       \
            _Pragma("unroll")                                             \
            for (int j = 0; j < 8; j++) acc[i][j] += ar[i]*br[j];         \
    }                                                                     \
    __syncthreads();

// A normal (row-major, lda): load transposed into As[k][m]
#define LOAD_A_N(Aptr, lda, kt)                                                   \
    {   int aRow = tid >> 1, aCol = (tid & 1) << 2;                               \
        float4 av = *(const float4*)((Aptr) + (size_t)(m0+aRow)*(lda) + (kt) + aCol); \
        As[aCol+0][aRow]=av.x; As[aCol+1][aRow]=av.y;                             \
        As[aCol+2][aRow]=av.z; As[aCol+3][aRow]=av.w; }

// A transposed source (As[k][m] = Aptr[(kt+k)*lda + m0+m])
#define LOAD_A_T(Aptr, lda, kt)                                                   \
    {   int aR = tid >> 5, aC = (tid & 31) << 2;                                  \
        float4 av = *(const float4*)((Aptr) + (size_t)((kt)+aR)*(lda) + m0 + aC); \
        *(float4*)(&As[aR][aC]) = av; }

// B normal (row-major [K,N], ldb)
#define LOAD_B_N(Bptr, ldb, kt)                                                   \
    {   int bR = tid >> 5, bC = (tid & 31) << 2;                                  \
        float4 bv = *(const float4*)((Bptr) + (size_t)((kt)+bR)*(ldb) + n0 + bC); \
        *(float4*)(&Bs[bR][bC]) = bv; }

// B transposed source (Bs[k][n] = Bptr[(n0+n)*ldb + kt+k])
#define LOAD_B_T(Bptr, ldb, kt)                                                   \
    {   int bN = tid >> 1, bK = (tid & 1) << 2;                                   \
        float4 bv = *(const float4*)((Bptr) + (size_t)(n0+bN)*(ldb) + (kt) + bK); \
        Bs[bK+0][bN]=bv.x; Bs[bK+1][bN]=bv.y; Bs[bK+2][bN]=bv.z; Bs[bK+3][bN]=bv.w; }

// =====================================================================
// Kernel 1: QKV projection. C = hidden @ W, epilogue splits heads and
// computes sigma = elu+1.  mode: 0=q, 1=k, 2=v
// =====================================================================
__global__ void k_qkv(const float* __restrict__ A, const float* __restrict__ W, int mode)
{
    int m0 = blockIdx.y * 128;
    int n0 = blockIdx.x * 128;
    GEMM_PROLOGUE();
    for (int kt = 0; kt < Ez; kt += 8) {
        LOAD_A_N(A, Ez, kt);
        LOAD_B_N(W, Ez, kt);
        GEMM_COMPUTE();
    }
    float* raw = (mode == 0) ? g_q : (mode == 1) ? g_k : g_v;
    float* sig = (mode == 0) ? g_sq : g_sk;
#pragma unroll
    for (int i = 0; i < 8; i++) {
        int m = m0 + ty*8 + i;
        int b = m >> 11, s = m & (Sz-1);
#pragma unroll
        for (int j = 0; j < 8; j++) {
            int n = n0 + tx*8 + j;
            int h = n >> 8, d = n & (Dz-1);
            size_t idx = ((size_t)((b*Hz + h)*Sz + s) << 8) | (size_t)d;
            float v = acc[i][j];
            raw[idx] = v;
            if (mode != 2) sig[idx] = (v > 0.f) ? (v + 1.f) : expf(v);
        }
    }
}

// =====================================================================
// Kernel 2: denominators  den = sigma . z + 1e-6  (warp per row)
// =====================================================================
__global__ void k_denom(const float* __restrict__ z)
{
    int tid = threadIdx.x;
    int lane = tid & 31;
    int row = blockIdx.x * 8 + (tid >> 5);      // bh*Sz + s, < 32768
    int h = (row >> 11) & (Hz-1);
    const float* zr = z + h*Dz;
    const float* sq = g_sq + (size_t)row*Dz;
    const float* sk = g_sk + (size_t)row*Dz;
    float s1 = 0.f, s2 = 0.f;
#pragma unroll
    for (int d = lane; d < Dz; d += 32) {
        float zz = zr[d];
        s1 += sq[d]*zz;
        s2 += sk[d]*zz;
    }
#pragma unroll
    for (int o = 16; o > 0; o >>= 1) {
        s1 += __shfl_xor_sync(0xffffffffu, s1, o);
        s2 += __shfl_xor_sync(0xffffffffu, s2, o);
    }
    if (lane == 0) {
        g_qden[row] = s1 + 1e-6f;
        g_kden[row] = s2 + 1e-6f;
    }
}

// =====================================================================
// Kernel 3: A_mem = (sigma_q @ mem)/den * gate, into g_attnmix [B,S,E]
// batched over bh (blockIdx.z), M=2048 N=256 K=256
// =====================================================================
__global__ void k_amem(const float* __restrict__ mem, const float* __restrict__ betas)
{
    int bh = blockIdx.z;
    int h = bh & (Hz-1), b = bh >> 2;
    const float* A  = g_sq + (size_t)bh*Sz*Dz;
    const float* Bm = mem + (size_t)h*Dz*Dz;
    int m0 = blockIdx.y * 128;
    int n0 = blockIdx.x * 128;
    GEMM_PROLOGUE();
    for (int kt = 0; kt < Dz; kt += 8) {
        LOAD_A_N(A, Dz, kt);
        LOAD_B_N(Bm, Dz, kt);
        GEMM_COMPUTE();
    }
    float gate = 1.f / (1.f + expf(-betas[h]));
#pragma unroll
    for (int i = 0; i < 8; i++) {
        int m = m0 + ty*8 + i;                       // s
        float inv = gate / g_qden[bh*Sz + m];
#pragma unroll
        for (int j = 0; j < 8; j++) {
            int n = n0 + tx*8 + j;                   // e
            g_attnmix[((size_t)(b*Sz + m))*Ez + h*Dz + n] = acc[i][j] * inv;
        }
    }
}

// =====================================================================
// Kernel 4: delta & u = v - (sigma_k @ mem)/den_k
// =====================================================================
__global__ void k_deltau(const float* __restrict__ mem)
{
    int bh = blockIdx.z;
    int h = bh & (Hz-1);
    const float* A  = g_sk + (size_t)bh*Sz*Dz;
    const float* Bm = mem + (size_t)h*Dz*Dz;
    int m0 = blockIdx.y * 128;
    int n0 = blockIdx.x * 128;
    GEMM_PROLOGUE();
    for (int kt = 0; kt < Dz; kt += 8) {
        LOAD_A_N(A, Dz, kt);
        LOAD_B_N(Bm, Dz, kt);
        GEMM_COMPUTE();
    }
#pragma unroll
    for (int i = 0; i < 8; i++) {
        int m = m0 + ty*8 + i;
        float inv = 1.f / g_kden[bh*Sz + m];
#pragma unroll
        for (int j = 0; j < 8; j++) {
            int n = n0 + tx*8 + j;
            size_t idx = ((size_t)bh*Sz + m)*Dz + n;
            g_u[idx] = g_v[idx] - acc[i][j]*inv;
        }
    }
}

// =====================================================================
// Kernel 5: scores = q @ k^T with causal mask (skip fully-masked blocks)
// =====================================================================
__global__ void k_scores()
{
    int bh = blockIdx.z;
    int m0 = blockIdx.y * 128;
    int n0 = blockIdx.x * 128;
    float* Srow = g_scores + (size_t)bh*Sz*Sz;
    int tid = threadIdx.x;
    int ty = tid >> 4, tx = tid & 15;
    if (n0 > m0) {   // whole 128x128 block strictly above diagonal
#pragma unroll
        for (int i = 0; i < 8; i++) {
            int m = m0 + ty*8 + i;
#pragma unroll
            for (int j = 0; j < 8; j++)
                Srow[(size_t)m*Sz + n0 + tx*8 + j] = MASKVAL;
        }
        return;
    }
    const float* Q  = g_q + (size_t)bh*Sz*Dz;
    const float* Kp = g_k + (size_t)bh*Sz*Dz;
    __shared__ float As[8][128];
    __shared__ float Bs[8][128];
    float acc[8][8];
#pragma unroll
    for (int i = 0; i < 8; i++)
#pragma unroll
        for (int j = 0; j < 8; j++) acc[i][j] = 0.f;
    for (int kt = 0; kt < Dz; kt += 8) {
        LOAD_A_N(Q, Dz, kt);
        LOAD_B_T(Kp, Dz, kt);
        GEMM_COMPUTE();
    }
#pragma unroll
    for (int i = 0; i < 8; i++) {
        int m = m0 + ty*8 + i;
#pragma unroll
        for (int j = 0; j < 8; j++) {
            int n = n0 + tx*8 + j;
            Srow[(size_t)m*Sz + n] = (n <= m) ? acc[i][j] : MASKVAL;
        }
    }
}

// =====================================================================
// Kernel 6: row softmax (register-resident, one block per row)
// =====================================================================
__global__ void k_softmax()
{
    float* p = g_scores + (size_t)blockIdx.x * Sz;
    int tid = threadIdx.x;
    float r[8];
#pragma unroll
    for (int i = 0; i < 8; i++) r[i] = p[tid + i*256];
    float mx = r[0];
#pragma unroll
    for (int i = 1; i < 8; i++) mx = fmaxf(mx, r[i]);
    __shared__ float red[256];
    red[tid] = mx; __syncthreads();
    for (int s = 128; s > 0; s >>= 1) {
        if (tid < s) red[tid] = fmaxf(red[tid], red[tid+s]);
        __syncthreads();
    }
    mx = red[0]; __syncthreads();
    float sum = 0.f;
#pragma unroll
    for (int i = 0; i < 8; i++) { r[i] = expf(r[i] - mx); sum += r[i]; }
    red[tid] = sum; __syncthreads();
    for (int s = 128; s > 0; s >>= 1) {
        if (tid < s) red[tid] += red[tid+s];
        __syncthreads();
    }
    float inv = 1.f / red[0];
#pragma unroll
    for (int i = 0; i < 8; i++) p[tid + i*256] = r[i]*inv;
}

// =====================================================================
// Kernel 7: O = P @ V (causal K-limit), attnmix += (1-gate)*O
// =====================================================================
__global__ void k_pv(const float* __restrict__ betas)
{
    int bh = blockIdx.z;
    int h = bh & (Hz-1), b = bh >> 2;
    const float* P = g_scores + (size_t)bh*Sz*Sz;
    const float* V = g_v + (size_t)bh*Sz*Dz;
    int m0 = blockIdx.y * 128;
    int n0 = blockIdx.x * 128;
    int Klim = m0 + 128;     // P[m,n] == 0 for n > m
    GEMM_PROLOGUE();
    for (int kt = 0; kt < Klim; kt += 8) {
        LOAD_A_N(P, Sz, kt);
        LOAD_B_N(V, Dz, kt);
        GEMM_COMPUTE();
    }
    float og = 1.f - 1.f / (1.f + expf(-betas[h]));
#pragma unroll
    for (int i = 0; i < 8; i++) {
        int m = m0 + ty*8 + i;
#pragma unroll
        for (int j = 0; j < 8; j++) {
            int n = n0 + tx*8 + j;
            size_t idx = ((size_t)(b*Sz + m))*Ez + h*Dz + n;
            g_attnmix[idx] += og * acc[i][j];
        }
    }
}

// =====================================================================
// Kernel 8: mem_new[b,h] = mem[h] + sigma_k^T @ u   (M=N=256, K=2048)
// =====================================================================
__global__ void k_memupd(const float* __restrict__ mem, float* __restrict__ out)
{
    int bh = blockIdx.z;
    int h = bh & (Hz-1);
    const float* Ask = g_sk + (size_t)bh*Sz*Dz;   // transposed access
    const float* U   = g_u + (size_t)bh*Sz*Dz;
    int m0 = blockIdx.y * 128;
    int n0 = blockIdx.x * 128;
    GEMM_PROLOGUE();
    for (int kt = 0; kt < Sz; kt += 8) {
        LOAD_A_T(Ask, Dz, kt);
        LOAD_B_N(U, Dz, kt);
        GEMM_COMPUTE();
    }
#pragma unroll
    for (int i = 0; i < 8; i++) {
        int m = m0 + ty*8 + i;
#pragma unroll
        for (int j = 0; j < 8; j++) {
            int n = n0 + tx*8 + j;
            out[(size_t)bh*Dz*Dz + (size_t)m*Dz + n] =
                mem[(size_t)h*Dz*Dz + (size_t)m*Dz + n] + acc[i][j];
        }
    }
}

// =====================================================================
// Kernel 9: z_new = z + sum_s sigma_k
// =====================================================================
__global__ void k_znew(const float* __restrict__ z, float* __restrict__ out)
{
    int bh = blockIdx.x;
    int h = bh & (Hz-1);
    int d = threadIdx.x;
    const float* sk = g_sk + (size_t)bh*Sz*Dz;
    float s = 0.f;
    for (int i = 0; i < Sz; i++) s += sk[(size_t)i*Dz + d];
    out[bh*Dz + d] = z[h*Dz + d] + s;
}

// =====================================================================
// Kernel 10: out = attnmix @ Wo + bo
// =====================================================================
__global__ void k_out(const float* __restrict__ Wo, const float* __restrict__ bo,
                      float* __restrict__ out)
{
    const float* A = g_attnmix;
    int m0 = blockIdx.y * 128;
    int n0 = blockIdx.x * 128;
    GEMM_PROLOGUE();
    for (int kt = 0; kt < Ez; kt += 8) {
        LOAD_A_N(A, Ez, kt);
        LOAD_B_N(Wo, Ez, kt);
        GEMM_COMPUTE();
    }
#pragma unroll
    for (int i = 0; i < 8; i++) {
        int m = m0 + ty*8 + i;
#pragma unroll
        for (int j = 0; j < 8; j++) {
            int n = n0 + tx*8 + j;
            out[(size_t)m*Ez + n] = acc[i][j] + bo[n];
        }
    }
}

// =====================================================================
extern "C" void kernel_launch(void* const* d_in, const int* in_sizes, int n_in,
                              void* d_out, int out_size)
{
    (void)in_sizes; (void)n_in;
    const float* hid   = (const float*)d_in[0];
    const float* Wq    = (const float*)d_in[1];
    const float* Wk    = (const float*)d_in[2];
    const float* Wv    = (const float*)d_in[3];
    const float* Wo    = (const float*)d_in[4];
    const float* bo    = (const float*)d_in[5];
    const float* betas = (const float*)d_in[6];
    const float* mem   = (const float*)d_in[7];
    const float* z     = (const float*)d_in[8];
    float* out = (float*)d_out;

    k_qkv<<<dim3(8, 64), 256>>>(hid, Wq, 0);
    k_qkv<<<dim3(8, 64), 256>>>(hid, Wk, 1);
    k_qkv<<<dim3(8, 64), 256>>>(hid, Wv, 2);
    k_denom<<<4096, 256>>>(z);
    k_amem<<<dim3(2, 16, BHz), 256>>>(mem, betas);
    k_scores<<<dim3(16, 16, BHz), 256>>>();
    k_softmax<<<BHz*Sz, 256>>>();
    k_pv<<<dim3(2, 16, BHz), 256>>>(betas);
    k_out<<<dim3(8, 64), 256>>>(Wo, bo, out);

    if (out_size >= OUT0 + MEMSZ) {
        k_deltau<<<dim3(2, 16, BHz), 256>>>(mem);
        k_memupd<<<dim3(2, 2, BHz), 256>>>(mem, out + OUT0);
    }
    if (out_size >= OUT0 + MEMSZ + ZSZ) {
        k_znew<<<BHz, 256>>>(z, out + OUT0 + MEMSZ);
    }
}

// round 3
// speedup vs baseline: 1.6843x; 1.6843x over previous
#include <cuda_runtime.h>
#include <cuda_fp16.h>
#include <math.h>
#include <stdint.h>

#define Bz 4
#define Sz 2048
#define Ez 1024
#define Hz 4
#define Dz 256
#define BHz (Bz*Hz)

#define OUT0  (Bz*Sz*Ez)          // 8388608
#define MEMSZ (Bz*Hz*Dz*Dz)       // 1048576
#define ZSZ   (Bz*Hz*Dz)          // 4096

#define NBIG (Bz*Hz*Sz*Dz)        // 8388608

// ---------------- scratch (static device arrays) ----------------
__device__ __half g_hid_hi[NBIG], g_hid_lo[NBIG];
__device__ __half g_wqT_hi[Ez*Ez], g_wqT_lo[Ez*Ez];
__device__ __half g_wkT_hi[Ez*Ez], g_wkT_lo[Ez*Ez];
__device__ __half g_wvT_hi[Ez*Ez], g_wvT_lo[Ez*Ez];
__device__ __half g_woT_hi[Ez*Ez], g_woT_lo[Ez*Ez];
__device__ __half g_memT_hi[Hz*Dz*Dz], g_memT_lo[Hz*Dz*Dz];

__device__ __half g_q_hi[NBIG],  g_q_lo[NBIG];
__device__ __half g_k_hi[NBIG],  g_k_lo[NBIG];
__device__ __half g_sq_hi[NBIG], g_sq_lo[NBIG];
__device__ __half g_sk_hi[NBIG], g_sk_lo[NBIG];
__device__ __half g_skT_hi[NBIG],g_skT_lo[NBIG];
__device__ __half g_v_hi[NBIG],  g_v_lo[NBIG];
__device__ __half g_vT_hi[NBIG], g_vT_lo[NBIG];
__device__ __half g_uT_hi[NBIG], g_uT_lo[NBIG];
__device__ __half g_mix_hi[NBIG],g_mix_lo[NBIG];

__device__ __half g_P_hi[(size_t)BHz*Sz*Sz];   // 134 MB
__device__ float  g_scores[(size_t)BHz*Sz*Sz]; // 268 MB
__device__ float  g_attnmix[Bz*Sz*Ez];
__device__ float  g_qden[BHz*Sz];
__device__ float  g_kden[BHz*Sz];

// ---------------- helpers ----------------
__device__ __forceinline__ uint32_t smem_to_u32(const void* p) {
    uint32_t a;
    asm("{ .reg .u64 t; cvta.to.shared.u64 t, %1; cvt.u32.u64 %0, t; }" : "=r"(a) : "l"(p));
    return a;
}
__device__ __forceinline__ uint32_t lds32(uint32_t addr){
    uint32_t v; asm volatile("ld.shared.b32 %0, [%1];" : "=r"(v) : "r"(addr)); return v;
}
__device__ __forceinline__ void cp8(uint32_t dst, const void* src){
    asm volatile("cp.async.ca.shared.global [%0], [%1], 8;" :: "r"(dst), "l"(src) : "memory");
}
__device__ __forceinline__ void cp_commit(){ asm volatile("cp.async.commit_group;" ::: "memory"); }
template<int N> __device__ __forceinline__ void cp_wait(){
    asm volatile("cp.async.wait_group %0;" :: "n"(N) : "memory");
}
__device__ __forceinline__ void mma16816(float* c, const uint32_t* a, const uint32_t* b){
    asm volatile("mma.sync.aligned.m16n8k16.row.col.f32.f16.f16.f32 "
        "{%0,%1,%2,%3}, {%4,%5,%6,%7}, {%8,%9}, {%0,%1,%2,%3};"
        : "+f"(c[0]), "+f"(c[1]), "+f"(c[2]), "+f"(c[3])
        : "r"(a[0]), "r"(a[1]), "r"(a[2]), "r"(a[3]), "r"(b[0]), "r"(b[1]));
}
__device__ __forceinline__ void split_h(float v, __half& h, __half& l){
    h = __float2half_rn(v);
    l = __float2half_rn(v - __half2float(h));
}
__device__ __forceinline__ void store_pair(__half* hp, __half* lp, size_t ix, float v0, float v1){
    __half h0,l0,h1,l1;
    split_h(v0,h0,l0); split_h(v1,h1,l1);
    *(__half2*)(hp+ix) = __halves2half2(h0,h1);
    *(__half2*)(lp+ix) = __halves2half2(l0,l1);
}

// frag byte offset inside a tile: row r (0..127, 64B rows), k16-step ks, extra unit eu
__device__ __forceinline__ uint32_t fragoff(int ks, int eu, int r, int t4){
    return (uint32_t)(r*64 + (((((ks<<2)+(t4>>1)+eu)) ^ (r&7))<<3) + ((t4&1)<<2));
}

// ---------------- GEMM core ----------------
// 128x128 CTA tile, 256 thr (8 warps, 2x4), k-chunk 32, double-buffered cp.async.
// A: [128 rows m][k] halves hi/lo, lda; B: [128 rows n][k] halves hi/lo, ldb.
// acc += Ahi*Bhi + Ahi*Blo (+ Alo*Bhi if USE_ALO).
#define SM_BYTES 65536

template<bool USE_ALO, class Epi>
__device__ __forceinline__ void gemm_core(
    const __half* __restrict__ Ahi, const __half* __restrict__ Alo, int lda,
    const __half* __restrict__ Bhi, const __half* __restrict__ Blo, int ldb,
    int K, Epi epi)
{
    extern __shared__ char smem[];
    uint32_t sb = smem_to_u32(smem);
    const int tid = threadIdx.x, wid = tid >> 5, lane = tid & 31;
    const int g = lane >> 2, t4 = lane & 3;
    const int wm = wid & 1, wn = wid >> 1;

    float acc[4][4][4];
#pragma unroll
    for (int i=0;i<4;i++)
#pragma unroll
    for (int j=0;j<4;j++)
#pragma unroll
    for (int q=0;q<4;q++) acc[i][j][q]=0.f;

    const int sr = tid >> 1;            // staging row 0..127
    const int cu0 = (tid & 1) * 4;      // first 8B unit
    const __half* aSrc  = Ahi + (size_t)sr*lda + cu0*4;
    const __half* alSrc = Alo + (size_t)sr*lda + cu0*4;
    const __half* bSrc  = Bhi + (size_t)sr*ldb + cu0*4;
    const __half* blSrc = Blo + (size_t)sr*ldb + cu0*4;
    uint32_t drow = sb + sr*64;
    uint32_t dus[4];
#pragma unroll
    for (int j=0;j<4;j++) dus[j] = (uint32_t)(((cu0+j) ^ (sr&7)) << 3);

    int iters = K >> 5;
    {   // stage chunk 0 into buffer 0
#pragma unroll
        for (int j=0;j<4;j++){
            cp8(drow + dus[j], aSrc + j*4);
            if (USE_ALO) cp8(drow + 8192 + dus[j], alSrc + j*4);
            cp8(drow + 16384 + dus[j], bSrc + j*4);
            cp8(drow + 24576 + dus[j], blSrc + j*4);
        }
        cp_commit();
    }
    for (int it=0; it<iters; it++){
        if (it+1 < iters){
            int kt = (it+1) << 5;
            uint32_t db = drow + ((it+1)&1)*32768u;
#pragma unroll
            for (int j=0;j<4;j++){
                cp8(db + dus[j], aSrc + kt + j*4);
                if (USE_ALO) cp8(db + 8192 + dus[j], alSrc + kt + j*4);
                cp8(db + 16384 + dus[j], bSrc + kt + j*4);
                cp8(db + 24576 + dus[j], blSrc + kt + j*4);
            }
            cp_commit();
            cp_wait<1>();
        } else {
            cp_wait<0>();
        }
        __syncthreads();
        uint32_t bb = sb + (it&1)*32768u;
#pragma unroll
        for (int ks=0; ks<2; ks++){
            uint32_t ah[4][4], al[4][4];
#pragma unroll
            for (int ma=0; ma<4; ma++){
                int r0 = wm*64 + ma*16 + g, r1 = r0+8;
                ah[ma][0] = lds32(bb + fragoff(ks,0,r0,t4));
                ah[ma][1] = lds32(bb + fragoff(ks,0,r1,t4));
                ah[ma][2] = lds32(bb + fragoff(ks,2,r0,t4));
                ah[ma][3] = lds32(bb + fragoff(ks,2,r1,t4));
                if (USE_ALO){
                    al[ma][0] = lds32(bb + 8192 + fragoff(ks,0,r0,t4));
                    al[ma][1] = lds32(bb + 8192 + fragoff(ks,0,r1,t4));
                    al[ma][2] = lds32(bb + 8192 + fragoff(ks,2,r0,t4));
                    al[ma][3] = lds32(bb + 8192 + fragoff(ks,2,r1,t4));
                }
            }
#pragma unroll
            for (int nb=0; nb<4; nb++){
                int nr = wn*32 + nb*8 + g;
                uint32_t bh[2], bl[2];
                bh[0] = lds32(bb + 16384 + fragoff(ks,0,nr,t4));
                bh[1] = lds32(bb + 16384 + fragoff(ks,2,nr,t4));
                bl[0] = lds32(bb + 24576 + fragoff(ks,0,nr,t4));
                bl[1] = lds32(bb + 24576 + fragoff(ks,2,nr,t4));
#pragma unroll
                for (int ma=0; ma<4; ma++){
                    mma16816(acc[ma][nb], ah[ma], bh);
                    mma16816(acc[ma][nb], ah[ma], bl);
                    if (USE_ALO) mma16816(acc[ma][nb], al[ma], bh);
                }
            }
        }
        __syncthreads();
    }
    // epilogue: epi(mr, nc, v0, v1) with nc, nc+1 consecutive cols
#pragma unroll
    for (int ma=0;ma<4;ma++){
        int mr = wm*64 + ma*16 + g;
#pragma unroll
        for (int nb=0;nb<4;nb++){
            int nc = wn*32 + nb*8 + 2*t4;
            epi(mr,   nc, acc[ma][nb][0], acc[ma][nb][1]);
            epi(mr+8, nc, acc[ma][nb][2], acc[ma][nb][3]);
        }
    }
}

// ---------------- prep kernels ----------------
__global__ __launch_bounds__(256) void k_prep_hid(const float* __restrict__ src)
{
    int i = (blockIdx.x*256 + threadIdx.x) * 4;
    float4 v = *(const float4*)(src + i);
    __half h,l;
    split_h(v.x,h,l); g_hid_hi[i+0]=h; g_hid_lo[i+0]=l;
    split_h(v.y,h,l); g_hid_hi[i+1]=h; g_hid_lo[i+1]=l;
    split_h(v.z,h,l); g_hid_hi[i+2]=h; g_hid_lo[i+2]=l;
    split_h(v.w,h,l); g_hid_hi[i+3]=h; g_hid_lo[i+3]=l;
}

// dst[n][k] = src[k][n], split to hi/lo. block (32,8), tile 32x32.
__global__ __launch_bounds__(256) void k_transpose_split(
    const float* __restrict__ src, __half* __restrict__ dhi, __half* __restrict__ dlo,
    int Kdim, int Ndim)
{
    __shared__ float tile[32][33];
    int n0 = blockIdx.x*32, k0 = blockIdx.y*32;
    size_t bo = (size_t)blockIdx.z * Kdim * Ndim;
    int tx = threadIdx.x & 31, ty = threadIdx.x >> 5;   // 32 x 8
#pragma unroll
    for (int j=0;j<32;j+=8)
        tile[ty+j][tx] = src[bo + (size_t)(k0+ty+j)*Ndim + n0+tx];
    __syncthreads();
#pragma unroll
    for (int j=0;j<32;j+=8){
        float v = tile[tx][ty+j];
        __half h,l; split_h(v,h,l);
        size_t o = bo + (size_t)(n0+ty+j)*Kdim + k0+tx;
        dhi[o]=h; dlo[o]=l;
    }
}

// ---------------- GEMM kernels ----------------

// QKV: C = hidden @ W (M 8192, N 1024, K 1024); blockIdx.z = mode (0 q,1 k,2 v)
__global__ __launch_bounds__(256) void k_qkv()
{
    int m0 = blockIdx.y*128, n0 = blockIdx.x*128;
    int mode = blockIdx.z;
    const __half *wh, *wl;
    if (mode==0){ wh=g_wqT_hi; wl=g_wqT_lo; }
    else if (mode==1){ wh=g_wkT_hi; wl=g_wkT_lo; }
    else { wh=g_wvT_hi; wl=g_wvT_lo; }
    const __half* Ah = g_hid_hi + (size_t)m0*Ez;
    const __half* Al = g_hid_lo + (size_t)m0*Ez;
    const __half* Bh = wh + (size_t)n0*Ez;
    const __half* Bl = wl + (size_t)n0*Ez;

    if (mode == 0) {
        gemm_core<true>(Ah, Al, Ez, Bh, Bl, Ez, Ez,
            [&](int mr, int nc, float v0, float v1){
                int m = m0+mr, n = n0+nc;
                int b = m>>11, s = m&(Sz-1), h = n>>8, d = n&(Dz-1);
                size_t ix = ((size_t)((b*Hz+h)*Sz + s))*Dz + d;
                store_pair(g_q_hi, g_q_lo, ix, v0, v1);
                float s0 = (v0>0.f)? v0+1.f : expf(v0);
                float s1 = (v1>0.f)? v1+1.f : expf(v1);
                store_pair(g_sq_hi, g_sq_lo, ix, s0, s1);
            });
    } else if (mode == 1) {
        gemm_core<true>(Ah, Al, Ez, Bh, Bl, Ez, Ez,
            [&](int mr, int nc, float v0, float v1){
                int m = m0+mr, n = n0+nc;
                int b = m>>11, s = m&(Sz-1), h = n>>8, d = n&(Dz-1);
                int bh = b*Hz+h;
                size_t ix = ((size_t)bh*Sz + s)*Dz + d;
                store_pair(g_k_hi, g_k_lo, ix, v0, v1);
                float s0 = (v0>0.f)? v0+1.f : expf(v0);
                float s1 = (v1>0.f)? v1+1.f : expf(v1);
                store_pair(g_sk_hi, g_sk_lo, ix, s0, s1);
                // transposed sigma_k: [bh][d][s]
                size_t tix = ((size_t)bh*Dz + d)*Sz + s;
                __half h0,l0,h1,l1;
                split_h(s0,h0,l0); split_h(s1,h1,l1);
                g_skT_hi[tix]=h0; g_skT_lo[tix]=l0;
                g_skT_hi[tix+Sz]=h1; g_skT_lo[tix+Sz]=l1;
            });
    } else {
        gemm_core<true>(Ah, Al, Ez, Bh, Bl, Ez, Ez,
            [&](int mr, int nc, float v0, float v1){
                int m = m0+mr, n = n0+nc;
                int b = m>>11, s = m&(Sz-1), h = n>>8, d = n&(Dz-1);
                int bh = b*Hz+h;
                size_t ix = ((size_t)bh*Sz + s)*Dz + d;
                store_pair(g_v_hi, g_v_lo, ix, v0, v1);
                size_t tix = ((size_t)bh*Dz + d)*Sz + s;
                __half h0,l0,h1,l1;
                split_h(v0,h0,l0); split_h(v1,h1,l1);
                g_vT_hi[tix]=h0; g_vT_lo[tix]=l0;
                g_vT_hi[tix+Sz]=h1; g_vT_lo[tix+Sz]=l1;
            });
    }
}

// scores = q @ k^T (blocks above diagonal skipped)
__global__ __launch_bounds__(256) void k_scores()
{
    int n0 = blockIdx.x*128, m0 = blockIdx.y*128;
    if (n0 > m0) return;
    int bh = blockIdx.z;
    const __half* Ah = g_q_hi + ((size_t)bh*Sz + m0)*Dz;
    const __half* Al = g_q_lo + ((size_t)bh*Sz + m0)*Dz;
    const __half* Bh = g_k_hi + ((size_t)bh*Sz + n0)*Dz;
    const __half* Bl = g_k_lo + ((size_t)bh*Sz + n0)*Dz;
    float* Srow = g_scores + (size_t)bh*Sz*Sz;
    gemm_core<true>(Ah, Al, Dz, Bh, Bl, Dz, Dz,
        [&](int mr, int nc, float v0, float v1){
            *(float2*)(Srow + (size_t)(m0+mr)*Sz + n0+nc) = make_float2(v0,v1);
        });
}

// row softmax, writes P_hi halves zero-padded to Klim
__global__ __launch_bounds__(256) void k_softmax()
{
    int row = blockIdx.x;
    int rr = row & (Sz-1);
    const float* p = g_scores + (size_t)row*Sz;
    __half* ph = g_P_hi + (size_t)row*Sz;
    int tid = threadIdx.x;
    int Klim = ((rr>>7)+1)<<7;
    float rv[8];
    float mx = -INFINITY;
#pragma unroll
    for (int i=0;i<8;i++){
        int n = tid + i*256;
        rv[i] = (n <= rr) ? p[n] : -INFINITY;
        mx = fmaxf(mx, rv[i]);
    }
    __shared__ float red[256];
    red[tid]=mx; __syncthreads();
    for (int s=128;s>0;s>>=1){ if(tid<s) red[tid]=fmaxf(red[tid],red[tid+s]); __syncthreads(); }
    mx = red[0]; __syncthreads();
    float sum=0.f;
#pragma unroll
    for (int i=0;i<8;i++){ rv[i]=expf(rv[i]-mx); sum+=rv[i]; }
    red[tid]=sum; __syncthreads();
    for (int s=128;s>0;s>>=1){ if(tid<s) red[tid]+=red[tid+s]; __syncthreads(); }
    float inv = 1.f/red[0];
#pragma unroll
    for (int i=0;i<8;i++){
        int n = tid + i*256;
        if (n < Klim) ph[n] = __float2half_rn(rv[i]*inv);
    }
}

// denominators: sigma . z + 1e-6
__global__ __launch_bounds__(256) void k_denom(const float* __restrict__ z)
{
    int tid = threadIdx.x, lane = tid&31;
    int row = blockIdx.x*8 + (tid>>5);
    int h = (row>>11) & (Hz-1);
    const float* zr = z + h*Dz;
    const __half* qh = g_sq_hi + (size_t)row*Dz;
    const __half* ql = g_sq_lo + (size_t)row*Dz;
    const __half* kh = g_sk_hi + (size_t)row*Dz;
    const __half* kl = g_sk_lo + (size_t)row*Dz;
    float s1=0.f, s2=0.f;
#pragma unroll
    for (int d=lane; d<Dz; d+=32){
        float zz = zr[d];
        s1 += (__half2float(qh[d]) + __half2float(ql[d]))*zz;
        s2 += (__half2float(kh[d]) + __half2float(kl[d]))*zz;
    }
#pragma unroll
    for (int o=16;o>0;o>>=1){
        s1 += __shfl_xor_sync(0xffffffffu, s1, o);
        s2 += __shfl_xor_sync(0xffffffffu, s2, o);
    }
    if (lane==0){ g_qden[row]=s1+1e-6f; g_kden[row]=s2+1e-6f; }
}

// A_mem*gate -> attnmix (fp32)
__global__ __launch_bounds__(256) void k_amem(const float* __restrict__ betas)
{
    int bh = blockIdx.z, h = bh&(Hz-1), b = bh>>2;
    int m0 = blockIdx.y*128, n0 = blockIdx.x*128;
    const __half* Ah = g_sq_hi + ((size_t)bh*Sz + m0)*Dz;
    const __half* Al = g_sq_lo + ((size_t)bh*Sz + m0)*Dz;
    const __half* Bh = g_memT_hi + ((size_t)h*Dz + n0)*Dz;
    const __half* Bl = g_memT_lo + ((size_t)h*Dz + n0)*Dz;
    float gate = 1.f/(1.f+expf(-betas[h]));
    gemm_core<true>(Ah, Al, Dz, Bh, Bl, Dz, Dz,
        [&](int mr, int nc, float v0, float v1){
            int s = m0+mr;
            float inv = gate / g_qden[bh*Sz + s];
            size_t ix = ((size_t)(b*Sz+s))*Ez + h*Dz + n0+nc;
            *(float2*)(g_attnmix + ix) = make_float2(v0*inv, v1*inv);
        });
}

// O = P @ V^T-layout; mix = attnmix + (1-gate)*O, split -> mix hi/lo
__global__ __launch_bounds__(256) void k_pv(const float* __restrict__ betas)
{
    int bh = blockIdx.z, h = bh&(Hz-1), b = bh>>2;
    int m0 = blockIdx.y*128, n0 = blockIdx.x*128;
    const __half* Ah = g_P_hi + ((size_t)bh*Sz + m0)*Sz;
    const __half* Bh = g_vT_hi + ((size_t)bh*Dz + n0)*Sz;
    const __half* Bl = g_vT_lo + ((size_t)bh*Dz + n0)*Sz;
    float og = 1.f - 1.f/(1.f+expf(-betas[h]));
    gemm_core<false>(Ah, Ah, Sz, Bh, Bl, Sz, m0+128,
        [&](int mr, int nc, float v0, float v1){
            int s = m0+mr;
            size_t ix = ((size_t)(b*Sz+s))*Ez + h*Dz + n0+nc;
            float2 a = *(const float2*)(g_attnmix + ix);
            store_pair(g_mix_hi, g_mix_lo, ix, a.x + og*v0, a.y + og*v1);
        });
}

// u = v - (sigma_k @ mem)/kden, write transposed uT hi/lo
__global__ __launch_bounds__(256) void k_deltau()
{
    int bh = blockIdx.z, h = bh&(Hz-1);
    int m0 = blockIdx.y*128, n0 = blockIdx.x*128;
    const __half* Ah = g_sk_hi + ((size_t)bh*Sz + m0)*Dz;
    const __half* Al = g_sk_lo + ((size_t)bh*Sz + m0)*Dz;
    const __half* Bh = g_memT_hi + ((size_t)h*Dz + n0)*Dz;
    const __half* Bl = g_memT_lo + ((size_t)h*Dz + n0)*Dz;
    gemm_core<true>(Ah, Al, Dz, Bh, Bl, Dz, Dz,
        [&](int mr, int nc, float v0, float v1){
            int s = m0+mr, d = n0+nc;
            float inv = 1.f / g_kden[bh*Sz + s];
            size_t vix = ((size_t)bh*Sz + s)*Dz + d;
            float vv0 = __half2float(g_v_hi[vix])   + __half2float(g_v_lo[vix]);
            float vv1 = __half2float(g_v_hi[vix+1]) + __half2float(g_v_lo[vix+1]);
            float u0 = vv0 - v0*inv, u1 = vv1 - v1*inv;
            size_t tix = ((size_t)bh*Dz + d)*Sz + s;
            __half h0,l0,h1,l1;
            split_h(u0,h0,l0); split_h(u1,h1,l1);
            g_uT_hi[tix]=h0; g_uT_lo[tix]=l0;
            g_uT_hi[tix+Sz]=h1; g_uT_lo[tix+Sz]=l1;
        });
}

// mem_new = mem + sigma_k^T @ u  (M=N=256, K=2048)
__global__ __launch_bounds__(256) void k_memupd(const float* __restrict__ mem,
                                                float* __restrict__ outm)
{
    int bh = blockIdx.z, h = bh&(Hz-1);
    int m0 = blockIdx.y*128, n0 = blockIdx.x*128;
    const __half* Ah = g_skT_hi + ((size_t)bh*Dz + m0)*Sz;
    const __half* Al = g_skT_lo + ((size_t)bh*Dz + m0)*Sz;
    const __half* Bh = g_uT_hi + ((size_t)bh*Dz + n0)*Sz;
    const __half* Bl = g_uT_lo + ((size_t)bh*Dz + n0)*Sz;
    gemm_core<true>(Ah, Al, Sz, Bh, Bl, Sz, Sz,
        [&](int mr, int nc, float v0, float v1){
            int m = m0+mr, n = n0+nc;
            size_t ob = (size_t)bh*Dz*Dz + (size_t)m*Dz + n;
            size_t mb = (size_t)h*Dz*Dz + (size_t)m*Dz + n;
            float2 mm = *(const float2*)(mem + mb);
            *(float2*)(outm + ob) = make_float2(mm.x+v0, mm.y+v1);
        });
}

// out = mix @ Wo + bo
__global__ __launch_bounds__(256) void k_out(const float* __restrict__ bo,
                                             float* __restrict__ outp)
{
    int m0 = blockIdx.y*128, n0 = blockIdx.x*128;
    const __half* Ah = g_mix_hi + (size_t)m0*Ez;
    const __half* Al = g_mix_lo + (size_t)m0*Ez;
    const __half* Bh = g_woT_hi + (size_t)n0*Ez;
    const __half* Bl = g_woT_lo + (size_t)n0*Ez;
    gemm_core<true>(Ah, Al, Ez, Bh, Bl, Ez, Ez,
        [&](int mr, int nc, float v0, float v1){
            int m = m0+mr, n = n0+nc;
            float2 bb = *(const float2*)(bo + n);
            *(float2*)(outp + (size_t)m*Ez + n) = make_float2(v0+bb.x, v1+bb.y);
        });
}

// z_new = z + sum_s sigma_k
__global__ __launch_bounds__(256) void k_znew(const float* __restrict__ z,
                                              float* __restrict__ outz)
{
    int bh = blockIdx.x, h = bh&(Hz-1);
    int d = threadIdx.x;
    const __half* kh = g_sk_hi + (size_t)bh*Sz*Dz + d;
    const __half* kl = g_sk_lo + (size_t)bh*Sz*Dz + d;
    float s = 0.f;
    for (int i=0;i<Sz;i++)
        s += __half2float(kh[(size_t)i*Dz]) + __half2float(kl[(size_t)i*Dz]);
    outz[bh*Dz + d] = z[h*Dz + d] + s;
}

// ---------------- launch ----------------
static inline void set_smem(const void* f) {
    cudaFuncSetAttribute(f, cudaFuncAttributeMaxDynamicSharedMemorySize, SM_BYTES);
}

extern "C" void kernel_launch(void* const* d_in, const int* in_sizes, int n_in,
                              void* d_out, int out_size)
{
    (void)in_sizes; (void)n_in;
    const float* hid   = (const float*)d_in[0];
    const float* Wq    = (const float*)d_in[1];
    const float* Wk    = (const float*)d_in[2];
    const float* Wv    = (const float*)d_in[3];
    const float* Wo    = (const float*)d_in[4];
    const float* bo    = (const float*)d_in[5];
    const float* betas = (const float*)d_in[6];
    const float* mem   = (const float*)d_in[7];
    const float* z     = (const float*)d_in[8];
    float* out = (float*)d_out;

    static int once = 0;
    if (!once) {
        set_smem((const void*)k_qkv);
        set_smem((const void*)k_scores);
        set_smem((const void*)k_amem);
        set_smem((const void*)k_pv);
        set_smem((const void*)k_deltau);
        set_smem((const void*)k_memupd);
        set_smem((const void*)k_out);
        once = 1;
    }

    __half *wqh, *wql, *wkh, *wkl, *wvh, *wvl, *woh, *wol, *mth, *mtl;
    cudaGetSymbolAddress((void**)&wqh, g_wqT_hi); cudaGetSymbolAddress((void**)&wql, g_wqT_lo);
    cudaGetSymbolAddress((void**)&wkh, g_wkT_hi); cudaGetSymbolAddress((void**)&wkl, g_wkT_lo);
    cudaGetSymbolAddress((void**)&wvh, g_wvT_hi); cudaGetSymbolAddress((void**)&wvl, g_wvT_lo);
    cudaGetSymbolAddress((void**)&woh, g_woT_hi); cudaGetSymbolAddress((void**)&wol, g_woT_lo);
    cudaGetSymbolAddress((void**)&mth, g_memT_hi); cudaGetSymbolAddress((void**)&mtl, g_memT_lo);

    k_prep_hid<<<NBIG/1024, 256>>>(hid);
    k_transpose_split<<<dim3(32,32,1), 256>>>(Wq, wqh, wql, Ez, Ez);
    k_transpose_split<<<dim3(32,32,1), 256>>>(Wk, wkh, wkl, Ez, Ez);
    k_transpose_split<<<dim3(32,32,1), 256>>>(Wv, wvh, wvl, Ez, Ez);
    k_transpose_split<<<dim3(32,32,1), 256>>>(Wo, woh, wol, Ez, Ez);
    k_transpose_split<<<dim3(8,8,Hz), 256>>>(mem, mth, mtl, Dz, Dz);

    k_qkv<<<dim3(8,64,3), 256, SM_BYTES>>>();
    k_denom<<<4096, 256>>>(z);
    k_scores<<<dim3(16,16,BHz), 256, SM_BYTES>>>();
    k_softmax<<<BHz*Sz, 256>>>();
    k_amem<<<dim3(2,16,BHz), 256, SM_BYTES>>>(betas);
    k_pv<<<dim3(2,16,BHz), 256, SM_BYTES>>>(betas);
    k_out<<<dim3(8,64), 256, SM_BYTES>>>(bo, out);

    if (out_size >= OUT0 + MEMSZ) {
        k_deltau<<<dim3(2,16,BHz), 256, SM_BYTES>>>();
        k_memupd<<<dim3(2,2,BHz), 256, SM_BYTES>>>(mem, out + OUT0);
    }
    if (out_size >= OUT0 + MEMSZ + ZSZ) {
        k_znew<<<BHz, 256>>>(z, out + OUT0 + MEMSZ);
    }
}

// round 4
// speedup vs baseline: 2.6552x; 1.5764x over previous
#include <cuda_runtime.h>
#include <cuda_fp16.h>
#include <math.h>
#include <stdint.h>

#define Bz 4
#define Sz 2048
#define Ez 1024
#define Hz 4
#define Dz 256
#define BHz (Bz*Hz)

#define OUT0  (Bz*Sz*Ez)          // 8388608
#define MEMSZ (Bz*Hz*Dz*Dz)       // 1048576
#define ZSZ   (Bz*Hz*Dz)          // 4096

#define NBIG (Bz*Hz*Sz*Dz)        // 8388608

// ---------------- scratch (static device arrays) ----------------
__device__ __half g_hid_hi[NBIG], g_hid_lo[NBIG];
__device__ __half g_wqT_hi[Ez*Ez], g_wqT_lo[Ez*Ez];
__device__ __half g_wkT_hi[Ez*Ez], g_wkT_lo[Ez*Ez];
__device__ __half g_wvT_hi[Ez*Ez], g_wvT_lo[Ez*Ez];
__device__ __half g_woT_hi[Ez*Ez], g_woT_lo[Ez*Ez];
__device__ __half g_memT_hi[Hz*Dz*Dz], g_memT_lo[Hz*Dz*Dz];

__device__ __half g_q_hi[NBIG],  g_q_lo[NBIG];
__device__ __half g_k_hi[NBIG],  g_k_lo[NBIG];
__device__ __half g_sq_hi[NBIG], g_sq_lo[NBIG];
__device__ __half g_sk_hi[NBIG], g_sk_lo[NBIG];
__device__ __half g_skT_hi[NBIG],g_skT_lo[NBIG];
__device__ __half g_v_hi[NBIG],  g_v_lo[NBIG];
__device__ __half g_vT_hi[NBIG], g_vT_lo[NBIG];
__device__ __half g_u_hi[NBIG],  g_u_lo[NBIG];
__device__ __half g_uT_hi[NBIG], g_uT_lo[NBIG];
__device__ __half g_mix_hi[NBIG],g_mix_lo[NBIG];

__device__ __half g_P_hi[(size_t)BHz*Sz*Sz];   // 134 MB
__device__ float  g_scores[(size_t)BHz*Sz*Sz]; // 268 MB
__device__ float  g_attnmix[Bz*Sz*Ez];
__device__ float  g_qden[BHz*Sz];
__device__ float  g_kden[BHz*Sz];

// ---------------- helpers ----------------
__device__ __forceinline__ uint32_t smem_to_u32(const void* p) {
    uint32_t a;
    asm("{ .reg .u64 t; cvta.to.shared.u64 t, %1; cvt.u32.u64 %0, t; }" : "=r"(a) : "l"(p));
    return a;
}
__device__ __forceinline__ void cp16(uint32_t dst, const void* src){
    asm volatile("cp.async.cg.shared.global [%0], [%1], 16;" :: "r"(dst), "l"(src) : "memory");
}
__device__ __forceinline__ void cp_commit(){ asm volatile("cp.async.commit_group;" ::: "memory"); }
template<int N> __device__ __forceinline__ void cp_wait(){
    asm volatile("cp.async.wait_group %0;" :: "n"(N) : "memory");
}
__device__ __forceinline__ void ldsm4(uint32_t* r, uint32_t addr){
    asm volatile("ldmatrix.sync.aligned.m8n8.x4.shared.b16 {%0,%1,%2,%3}, [%4];"
        : "=r"(r[0]), "=r"(r[1]), "=r"(r[2]), "=r"(r[3]) : "r"(addr));
}
__device__ __forceinline__ void mma16816(float* c, const uint32_t* a, const uint32_t* b){
    asm volatile("mma.sync.aligned.m16n8k16.row.col.f32.f16.f16.f32 "
        "{%0,%1,%2,%3}, {%4,%5,%6,%7}, {%8,%9}, {%0,%1,%2,%3};"
        : "+f"(c[0]), "+f"(c[1]), "+f"(c[2]), "+f"(c[3])
        : "r"(a[0]), "r"(a[1]), "r"(a[2]), "r"(a[3]), "r"(b[0]), "r"(b[1]));
}
__device__ __forceinline__ void split_h(float v, __half& h, __half& l){
    h = __float2half_rn(v);
    l = __float2half_rn(v - __half2float(h));
}
__device__ __forceinline__ void store_pair(__half* hp, __half* lp, size_t ix, float v0, float v1){
    __half h0,l0,h1,l1;
    split_h(v0,h0,l0); split_h(v1,h1,l1);
    *(__half2*)(hp+ix) = __halves2half2(h0,h1);
    *(__half2*)(lp+ix) = __halves2half2(l0,l1);
}
// 16B-unit swizzle within a 128x32-half tile (64B rows, 4 units/row)
__device__ __forceinline__ uint32_t swz16(int r, int c16){
    return (uint32_t)(r*64 + ((c16 ^ (r&3) ^ ((r>>2)&3)) << 4));
}

// ---------------- GEMM core ----------------
// 128x128 CTA tile, 256 thr (8 warps 2x4, warp tile 64x32), k-chunk 32,
// double-buffered cp.async, ldmatrix operand loads.
// A: [128 m rows][k] hi/lo; B: [128 n rows][k] hi/lo.
// acc += Ahi*Bhi + Ahi*Blo (+ Alo*Bhi if USE_ALO)
#define SM_BYTES 65536

template<bool USE_ALO, class Epi>
__device__ __forceinline__ void gemm_core(
    const __half* __restrict__ Ahi, const __half* __restrict__ Alo, int lda,
    const __half* __restrict__ Bhi, const __half* __restrict__ Blo, int ldb,
    int K, Epi epi)
{
    extern __shared__ char smem[];
    uint32_t sb = smem_to_u32(smem);
    const int tid = threadIdx.x, wid = tid >> 5, lane = tid & 31;
    const int g = lane >> 2, t4 = lane & 3;
    const int wm = wid & 1, wn = wid >> 1;

    float acc[4][4][4];
#pragma unroll
    for (int i=0;i<4;i++)
#pragma unroll
    for (int j=0;j<4;j++)
#pragma unroll
    for (int q=0;q<4;q++) acc[i][j][q]=0.f;

    // staging: thread -> row sr, units c16a, c16a+1
    const int sr = tid >> 1;
    const int c16a = (tid & 1) * 2;
    const __half* aS  = Ahi + (size_t)sr*lda + c16a*8;
    const __half* alS = Alo + (size_t)sr*lda + c16a*8;
    const __half* bS  = Bhi + (size_t)sr*ldb + c16a*8;
    const __half* blS = Blo + (size_t)sr*ldb + c16a*8;
    const uint32_t s0 = swz16(sr, c16a);
    const uint32_t s1 = swz16(sr, c16a+1);

    // ldmatrix tile-relative offsets (ks=0); ks=1 -> off ^ 32
    uint32_t aOff[4], alOff[4], bOff[2], blOff[2];
    {
        int mi = lane >> 3, li = lane & 7;
#pragma unroll
        for (int ma=0;ma<4;ma++){
            int r = wm*64 + ma*16 + ((mi&1)<<3) + li;
            uint32_t o = swz16(r, mi>>1);
            aOff[ma] = o;  alOff[ma] = 8192 + o;
        }
#pragma unroll
        for (int nbp=0;nbp<2;nbp++){
            int n = wn*32 + nbp*16 + ((mi>>1)<<3) + li;
            uint32_t o = swz16(n, mi&1);
            bOff[nbp] = 16384 + o;  blOff[nbp] = 24576 + o;
        }
    }

    auto stage = [&](int kt, uint32_t boff){
        uint32_t d = sb + boff;
        cp16(d + s0, aS + kt);           cp16(d + s1, aS + kt + 8);
        if (USE_ALO){ cp16(d+8192+s0, alS+kt); cp16(d+8192+s1, alS+kt+8); }
        cp16(d+16384+s0, bS+kt);         cp16(d+16384+s1, bS+kt+8);
        cp16(d+24576+s0, blS+kt);        cp16(d+24576+s1, blS+kt+8);
    };

    int iters = K >> 5;
    stage(0, 0); cp_commit();
    for (int it=0; it<iters; it++){
        cp_wait<0>();
        __syncthreads();
        if (it+1 < iters){ stage((it+1)<<5, ((it+1)&1)*32768u); cp_commit(); }
        uint32_t base = sb + (it&1)*32768u;
#pragma unroll
        for (int ks=0; ks<2; ks++){
            uint32_t xk = (uint32_t)(ks<<5);
            uint32_t bh[8], bl[8];
            ldsm4(&bh[0], base + (bOff[0]^xk));
            ldsm4(&bh[4], base + (bOff[1]^xk));
            ldsm4(&bl[0], base + (blOff[0]^xk));
            ldsm4(&bl[4], base + (blOff[1]^xk));
#pragma unroll
            for (int ma=0; ma<4; ma++){
                uint32_t ah[4], al[4];
                ldsm4(ah, base + (aOff[ma]^xk));
                if (USE_ALO) ldsm4(al, base + (alOff[ma]^xk));
#pragma unroll
                for (int nb=0; nb<4; nb++){
                    mma16816(acc[ma][nb], ah, &bh[nb*2]);
                    mma16816(acc[ma][nb], ah, &bl[nb*2]);
                    if (USE_ALO) mma16816(acc[ma][nb], al, &bh[nb*2]);
                }
            }
        }
    }
    // epilogue
#pragma unroll
    for (int ma=0;ma<4;ma++){
        int mr = wm*64 + ma*16 + g;
#pragma unroll
        for (int nb=0;nb<4;nb++){
            int nc = wn*32 + nb*8 + 2*t4;
            epi(mr,   nc, acc[ma][nb][0], acc[ma][nb][1]);
            epi(mr+8, nc, acc[ma][nb][2], acc[ma][nb][3]);
        }
    }
}

// ---------------- prep kernels ----------------
__global__ __launch_bounds__(256) void k_prep_hid(const float* __restrict__ src)
{
    int i = (blockIdx.x*256 + threadIdx.x) * 4;
    float4 v = *(const float4*)(src + i);
    __half h,l;
    split_h(v.x,h,l); g_hid_hi[i+0]=h; g_hid_lo[i+0]=l;
    split_h(v.y,h,l); g_hid_hi[i+1]=h; g_hid_lo[i+1]=l;
    split_h(v.z,h,l); g_hid_hi[i+2]=h; g_hid_lo[i+2]=l;
    split_h(v.w,h,l); g_hid_hi[i+3]=h; g_hid_lo[i+3]=l;
}

// dst[n][k] = src[k][n], fp32 -> half hi/lo
__global__ __launch_bounds__(256) void k_transpose_split(
    const float* __restrict__ src, __half* __restrict__ dhi, __half* __restrict__ dlo,
    int Kdim, int Ndim)
{
    __shared__ float tile[32][33];
    int n0 = blockIdx.x*32, k0 = blockIdx.y*32;
    size_t bo = (size_t)blockIdx.z * Kdim * Ndim;
    int tx = threadIdx.x & 31, ty = threadIdx.x >> 5;
#pragma unroll
    for (int j=0;j<32;j+=8)
        tile[ty+j][tx] = src[bo + (size_t)(k0+ty+j)*Ndim + n0+tx];
    __syncthreads();
#pragma unroll
    for (int j=0;j<32;j+=8){
        float v = tile[tx][ty+j];
        __half h,l; split_h(v,h,l);
        size_t o = bo + (size_t)(n0+ty+j)*Kdim + k0+tx;
        dhi[o]=h; dlo[o]=l;
    }
}

// half transpose per bh: in [Sz][Dz] -> out [Dz][Sz], hi+lo together
__global__ __launch_bounds__(256) void k_transpose_h2(
    const __half* __restrict__ ih, const __half* __restrict__ il,
    __half* __restrict__ oh, __half* __restrict__ ol)
{
    __shared__ __half t[2][64][72];
    size_t base = (size_t)blockIdx.z * Sz * Dz;
    int s0 = blockIdx.y*64, d0 = blockIdx.x*64;
    int tr = threadIdx.x >> 3;        // 0..31
    int tc = (threadIdx.x & 7) * 8;   // 0..56
#pragma unroll
    for (int j=0;j<64;j+=32){
        *(float4*)&t[0][tr+j][tc] = *(const float4*)(ih + base + (size_t)(s0+tr+j)*Dz + d0+tc);
        *(float4*)&t[1][tr+j][tc] = *(const float4*)(il + base + (size_t)(s0+tr+j)*Dz + d0+tc);
    }
    __syncthreads();
#pragma unroll
    for (int j=0;j<64;j+=32){
        int dd = tr+j;
        __half a[8], b[8];
#pragma unroll
        for (int q=0;q<8;q++){ a[q]=t[0][tc+q][dd]; b[q]=t[1][tc+q][dd]; }
        size_t o = base + (size_t)(d0+dd)*Sz + s0+tc;
        *(float4*)(oh+o) = *(float4*)a;
        *(float4*)(ol+o) = *(float4*)b;
    }
}

// ---------------- GEMM kernels ----------------

// QKV: C = hidden @ W; blockIdx.z = mode (0 q, 1 k, 2 v)
__global__ __launch_bounds__(256,2) void k_qkv()
{
    int m0 = blockIdx.y*128, n0 = blockIdx.x*128;
    int mode = blockIdx.z;
    const __half *wh, *wl;
    if (mode==0){ wh=g_wqT_hi; wl=g_wqT_lo; }
    else if (mode==1){ wh=g_wkT_hi; wl=g_wkT_lo; }
    else { wh=g_wvT_hi; wl=g_wvT_lo; }
    const __half* Ah = g_hid_hi + (size_t)m0*Ez;
    const __half* Al = g_hid_lo + (size_t)m0*Ez;
    const __half* Bh = wh + (size_t)n0*Ez;
    const __half* Bl = wl + (size_t)n0*Ez;

    if (mode == 0) {
        gemm_core<true>(Ah, Al, Ez, Bh, Bl, Ez, Ez,
            [&](int mr, int nc, float v0, float v1){
                int m = m0+mr, n = n0+nc;
                int b = m>>11, s = m&(Sz-1), h = n>>8, d = n&(Dz-1);
                size_t ix = ((size_t)((b*Hz+h)*Sz + s))*Dz + d;
                store_pair(g_q_hi, g_q_lo, ix, v0, v1);
                float s0 = (v0>0.f)? v0+1.f : expf(v0);
                float s1 = (v1>0.f)? v1+1.f : expf(v1);
                store_pair(g_sq_hi, g_sq_lo, ix, s0, s1);
            });
    } else if (mode == 1) {
        gemm_core<true>(Ah, Al, Ez, Bh, Bl, Ez, Ez,
            [&](int mr, int nc, float v0, float v1){
                int m = m0+mr, n = n0+nc;
                int b = m>>11, s = m&(Sz-1), h = n>>8, d = n&(Dz-1);
                size_t ix = ((size_t)((b*Hz+h)*Sz + s))*Dz + d;
                store_pair(g_k_hi, g_k_lo, ix, v0, v1);
                float s0 = (v0>0.f)? v0+1.f : expf(v0);
                float s1 = (v1>0.f)? v1+1.f : expf(v1);
                store_pair(g_sk_hi, g_sk_lo, ix, s0, s1);
            });
    } else {
        gemm_core<true>(Ah, Al, Ez, Bh, Bl, Ez, Ez,
            [&](int mr, int nc, float v0, float v1){
                int m = m0+mr, n = n0+nc;
                int b = m>>11, s = m&(Sz-1), h = n>>8, d = n&(Dz-1);
                size_t ix = ((size_t)((b*Hz+h)*Sz + s))*Dz + d;
                store_pair(g_v_hi, g_v_lo, ix, v0, v1);
            });
    }
}

// scores = q @ k^T (blocks above diagonal skipped)
__global__ __launch_bounds__(256,2) void k_scores()
{
    int n0 = blockIdx.x*128, m0 = blockIdx.y*128;
    if (n0 > m0) return;
    int bh = blockIdx.z;
    const __half* Ah = g_q_hi + ((size_t)bh*Sz + m0)*Dz;
    const __half* Al = g_q_lo + ((size_t)bh*Sz + m0)*Dz;
    const __half* Bh = g_k_hi + ((size_t)bh*Sz + n0)*Dz;
    const __half* Bl = g_k_lo + ((size_t)bh*Sz + n0)*Dz;
    float* Srow = g_scores + (size_t)bh*Sz*Sz;
    gemm_core<true>(Ah, Al, Dz, Bh, Bl, Dz, Dz,
        [&](int mr, int nc, float v0, float v1){
            *(float2*)(Srow + (size_t)(m0+mr)*Sz + n0+nc) = make_float2(v0,v1);
        });
}

// row softmax, writes P_hi zero-padded to Klim
__global__ __launch_bounds__(256) void k_softmax()
{
    int row = blockIdx.x;
    int rr = row & (Sz-1);
    const float* p = g_scores + (size_t)row*Sz;
    __half* ph = g_P_hi + (size_t)row*Sz;
    int tid = threadIdx.x;
    int Klim = ((rr>>7)+1)<<7;
    float rv[8];
    float mx = -INFINITY;
#pragma unroll
    for (int i=0;i<8;i++){
        int n = tid + i*256;
        rv[i] = (n <= rr) ? p[n] : -INFINITY;
        mx = fmaxf(mx, rv[i]);
    }
    __shared__ float red[256];
    red[tid]=mx; __syncthreads();
    for (int s=128;s>0;s>>=1){ if(tid<s) red[tid]=fmaxf(red[tid],red[tid+s]); __syncthreads(); }
    mx = red[0]; __syncthreads();
    float sum=0.f;
#pragma unroll
    for (int i=0;i<8;i++){ rv[i]=expf(rv[i]-mx); sum+=rv[i]; }
    red[tid]=sum; __syncthreads();
    for (int s=128;s>0;s>>=1){ if(tid<s) red[tid]+=red[tid+s]; __syncthreads(); }
    float inv = 1.f/red[0];
#pragma unroll
    for (int i=0;i<8;i++){
        int n = tid + i*256;
        if (n < Klim) ph[n] = __float2half_rn(rv[i]*inv);
    }
}

// denominators: sigma . z + 1e-6
__global__ __launch_bounds__(256) void k_denom(const float* __restrict__ z)
{
    int tid = threadIdx.x, lane = tid&31;
    int row = blockIdx.x*8 + (tid>>5);
    int h = (row>>11) & (Hz-1);
    const float* zr = z + h*Dz;
    const __half* qh = g_sq_hi + (size_t)row*Dz;
    const __half* ql = g_sq_lo + (size_t)row*Dz;
    const __half* kh = g_sk_hi + (size_t)row*Dz;
    const __half* kl = g_sk_lo + (size_t)row*Dz;
    float s1=0.f, s2=0.f;
#pragma unroll
    for (int d=lane; d<Dz; d+=32){
        float zz = zr[d];
        s1 += (__half2float(qh[d]) + __half2float(ql[d]))*zz;
        s2 += (__half2float(kh[d]) + __half2float(kl[d]))*zz;
    }
#pragma unroll
    for (int o=16;o>0;o>>=1){
        s1 += __shfl_xor_sync(0xffffffffu, s1, o);
        s2 += __shfl_xor_sync(0xffffffffu, s2, o);
    }
    if (lane==0){ g_qden[row]=s1+1e-6f; g_kden[row]=s2+1e-6f; }
}

// A_mem*gate -> attnmix (fp32)
__global__ __launch_bounds__(256,2) void k_amem(const float* __restrict__ betas)
{
    int bh = blockIdx.z, h = bh&(Hz-1), b = bh>>2;
    int m0 = blockIdx.y*128, n0 = blockIdx.x*128;
    const __half* Ah = g_sq_hi + ((size_t)bh*Sz + m0)*Dz;
    const __half* Al = g_sq_lo + ((size_t)bh*Sz + m0)*Dz;
    const __half* Bh = g_memT_hi + ((size_t)h*Dz + n0)*Dz;
    const __half* Bl = g_memT_lo + ((size_t)h*Dz + n0)*Dz;
    float gate = 1.f/(1.f+expf(-betas[h]));
    gemm_core<true>(Ah, Al, Dz, Bh, Bl, Dz, Dz,
        [&](int mr, int nc, float v0, float v1){
            int s = m0+mr;
            float inv = gate / g_qden[bh*Sz + s];
            size_t ix = ((size_t)(b*Sz+s))*Ez + h*Dz + n0+nc;
            *(float2*)(g_attnmix + ix) = make_float2(v0*inv, v1*inv);
        });
}

// O = P @ vT; mix = attnmix + (1-gate)*O -> mix hi/lo
__global__ __launch_bounds__(256,2) void k_pv(const float* __restrict__ betas)
{
    int bh = blockIdx.z, h = bh&(Hz-1), b = bh>>2;
    int m0 = blockIdx.y*128, n0 = blockIdx.x*128;
    const __half* Ah = g_P_hi + ((size_t)bh*Sz + m0)*Sz;
    const __half* Bh = g_vT_hi + ((size_t)bh*Dz + n0)*Sz;
    const __half* Bl = g_vT_lo + ((size_t)bh*Dz + n0)*Sz;
    float og = 1.f - 1.f/(1.f+expf(-betas[h]));
    gemm_core<false>(Ah, Ah, Sz, Bh, Bl, Sz, m0+128,
        [&](int mr, int nc, float v0, float v1){
            int s = m0+mr;
            size_t ix = ((size_t)(b*Sz+s))*Ez + h*Dz + n0+nc;
            float2 a = *(const float2*)(g_attnmix + ix);
            store_pair(g_mix_hi, g_mix_lo, ix, a.x + og*v0, a.y + og*v1);
        });
}

// u = v - (sigma_k @ mem)/kden  (normal layout; transposed separately)
__global__ __launch_bounds__(256,2) void k_deltau()
{
    int bh = blockIdx.z, h = bh&(Hz-1);
    int m0 = blockIdx.y*128, n0 = blockIdx.x*128;
    const __half* Ah = g_sk_hi + ((size_t)bh*Sz + m0)*Dz;
    const __half* Al = g_sk_lo + ((size_t)bh*Sz + m0)*Dz;
    const __half* Bh = g_memT_hi + ((size_t)h*Dz + n0)*Dz;
    const __half* Bl = g_memT_lo + ((size_t)h*Dz + n0)*Dz;
    gemm_core<true>(Ah, Al, Dz, Bh, Bl, Dz, Dz,
        [&](int mr, int nc, float v0, float v1){
            int s = m0+mr, d = n0+nc;
            float inv = 1.f / g_kden[bh*Sz + s];
            size_t vix = ((size_t)bh*Sz + s)*Dz + d;
            float vv0 = __half2float(g_v_hi[vix])   + __half2float(g_v_lo[vix]);
            float vv1 = __half2float(g_v_hi[vix+1]) + __half2float(g_v_lo[vix+1]);
            store_pair(g_u_hi, g_u_lo, vix, vv0 - v0*inv, vv1 - v1*inv);
        });
}

// mem_new = mem + sigma_k^T @ u  (M=N=256, K=2048)
__global__ __launch_bounds__(256,2) void k_memupd(const float* __restrict__ mem,
                                                  float* __restrict__ outm)
{
    int bh = blockIdx.z, h = bh&(Hz-1);
    int m0 = blockIdx.y*128, n0 = blockIdx.x*128;
    const __half* Ah = g_skT_hi + ((size_t)bh*Dz + m0)*Sz;
    const __half* Al = g_skT_lo + ((size_t)bh*Dz + m0)*Sz;
    const __half* Bh = g_uT_hi + ((size_t)bh*Dz + n0)*Sz;
    const __half* Bl = g_uT_lo + ((size_t)bh*Dz + n0)*Sz;
    gemm_core<true>(Ah, Al, Sz, Bh, Bl, Sz, Sz,
        [&](int mr, int nc, float v0, float v1){
            int m = m0+mr, n = n0+nc;
            size_t ob = (size_t)bh*Dz*Dz + (size_t)m*Dz + n;
            size_t mb = (size_t)h*Dz*Dz + (size_t)m*Dz + n;
            float2 mm = *(const float2*)(mem + mb);
            *(float2*)(outm + ob) = make_float2(mm.x+v0, mm.y+v1);
        });
}

// out = mix @ Wo + bo
__global__ __launch_bounds__(256,2) void k_out(const float* __restrict__ bo,
                                               float* __restrict__ outp)
{
    int m0 = blockIdx.y*128, n0 = blockIdx.x*128;
    const __half* Ah = g_mix_hi + (size_t)m0*Ez;
    const __half* Al = g_mix_lo + (size_t)m0*Ez;
    const __half* Bh = g_woT_hi + (size_t)n0*Ez;
    const __half* Bl = g_woT_lo + (size_t)n0*Ez;
    gemm_core<true>(Ah, Al, Ez, Bh, Bl, Ez, Ez,
        [&](int mr, int nc, float v0, float v1){
            int m = m0+mr, n = n0+nc;
            float2 bb = *(const float2*)(bo + n);
            *(float2*)(outp + (size_t)m*Ez + n) = make_float2(v0+bb.x, v1+bb.y);
        });
}

// z_new = z + sum_s sigma_k
__global__ __launch_bounds__(256) void k_znew(const float* __restrict__ z,
                                              float* __restrict__ outz)
{
    int bh = blockIdx.x, h = bh&(Hz-1);
    int d = threadIdx.x;
    const __half* kh = g_sk_hi + (size_t)bh*Sz*Dz + d;
    const __half* kl = g_sk_lo + (size_t)bh*Sz*Dz + d;
    float s = 0.f;
    for (int i=0;i<Sz;i++)
        s += __half2float(kh[(size_t)i*Dz]) + __half2float(kl[(size_t)i*Dz]);
    outz[bh*Dz + d] = z[h*Dz + d] + s;
}

// ---------------- launch ----------------
static inline void set_smem(const void* f) {
    cudaFuncSetAttribute(f, cudaFuncAttributeMaxDynamicSharedMemorySize, SM_BYTES);
}

extern "C" void kernel_launch(void* const* d_in, const int* in_sizes, int n_in,
                              void* d_out, int out_size)
{
    (void)in_sizes; (void)n_in;
    const float* hid   = (const float*)d_in[0];
    const float* Wq    = (const float*)d_in[1];
    const float* Wk    = (const float*)d_in[2];
    const float* Wv    = (const float*)d_in[3];
    const float* Wo    = (const float*)d_in[4];
    const float* bo    = (const float*)d_in[5];
    const float* betas = (const float*)d_in[6];
    const float* mem   = (const float*)d_in[7];
    const float* z     = (const float*)d_in[8];
    float* out = (float*)d_out;

    set_smem((const void*)k_qkv);
    set_smem((const void*)k_scores);
    set_smem((const void*)k_amem);
    set_smem((const void*)k_pv);
    set_smem((const void*)k_deltau);
    set_smem((const void*)k_memupd);
    set_smem((const void*)k_out);

    __half *wqh, *wql, *wkh, *wkl, *wvh, *wvl, *woh, *wol, *mth, *mtl;
    cudaGetSymbolAddress((void**)&wqh, g_wqT_hi); cudaGetSymbolAddress((void**)&wql, g_wqT_lo);
    cudaGetSymbolAddress((void**)&wkh, g_wkT_hi); cudaGetSymbolAddress((void**)&wkl, g_wkT_lo);
    cudaGetSymbolAddress((void**)&wvh, g_wvT_hi); cudaGetSymbolAddress((void**)&wvl, g_wvT_lo);
    cudaGetSymbolAddress((void**)&woh, g_woT_hi); cudaGetSymbolAddress((void**)&wol, g_woT_lo);
    cudaGetSymbolAddress((void**)&mth, g_memT_hi); cudaGetSymbolAddress((void**)&mtl, g_memT_lo);

    __half *skh, *skl, *skTh, *skTl, *vh, *vl, *vTh, *vTl, *uh, *ul, *uTh, *uTl;
    cudaGetSymbolAddress((void**)&skh, g_sk_hi);  cudaGetSymbolAddress((void**)&skl, g_sk_lo);
    cudaGetSymbolAddress((void**)&skTh, g_skT_hi);cudaGetSymbolAddress((void**)&skTl, g_skT_lo);
    cudaGetSymbolAddress((void**)&vh, g_v_hi);    cudaGetSymbolAddress((void**)&vl, g_v_lo);
    cudaGetSymbolAddress((void**)&vTh, g_vT_hi);  cudaGetSymbolAddress((void**)&vTl, g_vT_lo);
    cudaGetSymbolAddress((void**)&uh, g_u_hi);    cudaGetSymbolAddress((void**)&ul, g_u_lo);
    cudaGetSymbolAddress((void**)&uTh, g_uT_hi);  cudaGetSymbolAddress((void**)&uTl, g_uT_lo);

    k_prep_hid<<<NBIG/1024, 256>>>(hid);
    k_transpose_split<<<dim3(32,32,1), 256>>>(Wq, wqh, wql, Ez, Ez);
    k_transpose_split<<<dim3(32,32,1), 256>>>(Wk, wkh, wkl, Ez, Ez);
    k_transpose_split<<<dim3(32,32,1), 256>>>(Wv, wvh, wvl, Ez, Ez);
    k_transpose_split<<<dim3(32,32,1), 256>>>(Wo, woh, wol, Ez, Ez);
    k_transpose_split<<<dim3(8,8,Hz), 256>>>(mem, mth, mtl, Dz, Dz);

    k_qkv<<<dim3(8,64,3), 256, SM_BYTES>>>();
    k_transpose_h2<<<dim3(4,32,BHz), 256>>>(vh, vl, vTh, vTl);
    k_denom<<<4096, 256>>>(z);
    k_scores<<<dim3(16,16,BHz), 256, SM_BYTES>>>();
    k_softmax<<<BHz*Sz, 256>>>();
    k_amem<<<dim3(2,16,BHz), 256, SM_BYTES>>>(betas);
    k_pv<<<dim3(2,16,BHz), 256, SM_BYTES>>>(betas);
    k_out<<<dim3(8,64), 256, SM_BYTES>>>(bo, out);

    if (out_size >= OUT0 + MEMSZ) {
        k_transpose_h2<<<dim3(4,32,BHz), 256>>>(skh, skl, skTh, skTl);
        k_deltau<<<dim3(2,16,BHz), 256, SM_BYTES>>>();
        k_transpose_h2<<<dim3(4,32,BHz), 256>>>(uh, ul, uTh, uTl);
        k_memupd<<<dim3(2,2,BHz), 256, SM_BYTES>>>(mem, out + OUT0);
    }
    if (out_size >= OUT0 + MEMSZ + ZSZ) {
        k_znew<<<BHz, 256>>>(z, out + OUT0 + MEMSZ);
    }
}